// round 4
// baseline (speedup 1.0000x reference)
#include <cuda_runtime.h>
#include <cuda_bf16.h>
#include <cuda_fp16.h>
#include <math.h>

// Problem constants
#define PP   256
#define FF   20
#define HH   18
#define WW   18
#define HW   (HH*WW)      // 324
#define VOL  (FF*HH*WW)   // 6480
#define MAXB 4096
#define ROWS 32
#define PI_F 3.14159f

// Padded pair volume: per layer 21 rows x 21 half2 (20 used + 1 pad), 20 layers
#define PROW 21
#define PLAY (PROW*PROW)  // 441
#define PVOL (FF*PLAY)    // 8820 half2 = 35280 B

// Raw per-(b,f) params: c, s, scale, tx, ty  (stride 5)
__device__ float g_params[MAXB * FF * 5];

// ---------------------------------------------------------------------------
// f32x2 helpers (FFMA2 via PTX)
// ---------------------------------------------------------------------------
typedef unsigned long long u64;

__device__ __forceinline__ u64 pack2dup(float v) {
    u64 d;
    asm("mov.b64 %0, {%1, %1};" : "=l"(d) : "r"(__float_as_uint(v)));
    return d;
}
__device__ __forceinline__ u64 fma2(u64 a, u64 b, u64 c) {
    u64 d;
    asm("fma.rn.f32x2 %0, %1, %2, %3;" : "=l"(d) : "l"(a), "l"(b), "l"(c));
    return d;
}
__device__ __forceinline__ float2 unpack2(u64 v) {
    unsigned lo, hi;
    asm("mov.b64 {%0, %1}, %2;" : "=r"(lo), "=r"(hi) : "l"(v));
    float2 f; f.x = __uint_as_float(lo); f.y = __uint_as_float(hi);
    return f;
}

// Dynamic smem layout (bytes) for params kernel:
//   pcs2 : float2[PP][18]  (row-pairs of pc, 16B-aligned slices) = 36864
//   hsm  : float [PP][33]  (h transposed: [hidden][row])         = 33792
#define PC_STRIDE 18
#define HS_STRIDE 33
#define OFF_HS   (PP * PC_STRIDE * 8)                  // 36864
#define SMEM_PAR (OFF_HS + PP * HS_STRIDE * 4)         // 70656

// ---------------------------------------------------------------------------
// Kernel 1: h = relu(pc @ W1 + b1); scale/angle/trans heads -> g_params.
// 32 rows/block, 256 threads. Phase 1: row-pair FFMA2, 4x4 u64 tile.
// ---------------------------------------------------------------------------
__global__ __launch_bounds__(256) void adaat_params_kernel(
    const float* __restrict__ pc, int B,
    const float* __restrict__ W1, const float* __restrict__ b1,
    const float* __restrict__ Ws, const float* __restrict__ bs,
    const float* __restrict__ Wr, const float* __restrict__ br,
    const float* __restrict__ Wt, const float* __restrict__ bt)
{
    extern __shared__ char smem_raw[];
    float2* pcs2 = (float2*)smem_raw;                 // [k][row-pair]
    float*  hsm  = (float*)(smem_raw + OFF_HS);       // [hidden][row]

    const int b0  = blockIdx.x * ROWS;
    const int tid = threadIdx.x;

    // ---- stage pc as row-pairs: pcs2[k][rpg] = (pc[2rpg][k], pc[2rpg+1][k]) ----
    #pragma unroll
    for (int i = tid; i < (ROWS / 2) * PP; i += 256) {
        int rpg = i >> 8;          // 0..15
        int k   = i & (PP - 1);
        int r0  = b0 + 2 * rpg;
        float v0 = (r0     < B) ? pc[(size_t)r0 * PP + k]       : 0.f;
        float v1 = (r0 + 1 < B) ? pc[(size_t)(r0 + 1) * PP + k] : 0.f;
        pcs2[k * PC_STRIDE + rpg] = make_float2(v0, v1);
    }
    __syncthreads();

    // ---- phase 1: 32 x 256 GEMM. thread tile: 4 row-pairs x 4 cols ----
    const int tr = tid >> 6;       // 0..3 -> row-pairs tr*4 .. +3 (rows tr*8..+7)
    const int tc = tid & 63;       // 0..63 -> cols tc*4 .. +3

    u64 acc[4][4];
    {
        float4 bj = *(const float4*)(b1 + tc * 4);
        u64 d0 = pack2dup(bj.x), d1 = pack2dup(bj.y);
        u64 d2 = pack2dup(bj.z), d3 = pack2dup(bj.w);
        #pragma unroll
        for (int rp = 0; rp < 4; rp++) {
            acc[rp][0] = d0; acc[rp][1] = d1; acc[rp][2] = d2; acc[rp][3] = d3;
        }
    }
    #pragma unroll 2
    for (int k = 0; k < PP; k++) {
        // 4 row-pairs (16B aligned: (k*18 + tr*4) is even)
        const ulonglong2* ap =
            (const ulonglong2*)(pcs2 + (size_t)k * PC_STRIDE + tr * 4);
        ulonglong2 q0 = ap[0], q1 = ap[1];
        u64 a0 = q0.x, a1 = q0.y, a2 = q1.x, a3 = q1.y;

        float4 w = *(const float4*)(W1 + (size_t)k * PP + tc * 4);
        u64 w0 = pack2dup(w.x), w1 = pack2dup(w.y);
        u64 w2 = pack2dup(w.z), w3 = pack2dup(w.w);

        acc[0][0] = fma2(a0, w0, acc[0][0]); acc[0][1] = fma2(a0, w1, acc[0][1]);
        acc[0][2] = fma2(a0, w2, acc[0][2]); acc[0][3] = fma2(a0, w3, acc[0][3]);
        acc[1][0] = fma2(a1, w0, acc[1][0]); acc[1][1] = fma2(a1, w1, acc[1][1]);
        acc[1][2] = fma2(a1, w2, acc[1][2]); acc[1][3] = fma2(a1, w3, acc[1][3]);
        acc[2][0] = fma2(a2, w0, acc[2][0]); acc[2][1] = fma2(a2, w1, acc[2][1]);
        acc[2][2] = fma2(a2, w2, acc[2][2]); acc[2][3] = fma2(a2, w3, acc[2][3]);
        acc[3][0] = fma2(a3, w0, acc[3][0]); acc[3][1] = fma2(a3, w1, acc[3][1]);
        acc[3][2] = fma2(a3, w2, acc[3][2]); acc[3][3] = fma2(a3, w3, acc[3][3]);
    }
    // ReLU + store transposed: hsm[hidden][row]
    #pragma unroll
    for (int rp = 0; rp < 4; rp++) {
        #pragma unroll
        for (int c = 0; c < 4; c++) {
            float2 v = unpack2(acc[rp][c]);
            int col  = tc * 4 + c;
            int row  = tr * 8 + 2 * rp;
            hsm[col * HS_STRIDE + row]     = fmaxf(v.x, 0.f);
            hsm[col * HS_STRIDE + row + 1] = fmaxf(v.y, 0.f);
        }
    }
    __syncthreads();

    // ---- phase 2: 32 rows x 20 float4 col-groups = 640 tasks.
    //      Head weights read from global (L1-shared across 8 rows). ----
    for (int t = tid; t < ROWS * 20; t += 256) {
        int r  = t / 20;
        int cg = t - r * 20;

        const float* Wp; float4 bb; int ld;
        if (cg < 5)       { Wp = Ws + cg * 4;        bb = ((const float4*)bs)[cg];      ld = 20; }
        else if (cg < 10) { Wp = Wr + (cg - 5) * 4;  bb = ((const float4*)br)[cg - 5];  ld = 20; }
        else              { Wp = Wt + (cg - 10) * 4; bb = ((const float4*)bt)[cg - 10]; ld = 40; }

        float o0 = bb.x, o1 = bb.y, o2 = bb.z, o3 = bb.w;
        const float* hp = hsm + r;
        #pragma unroll 4
        for (int k = 0; k < PP; k++) {
            float  h = hp[k * HS_STRIDE];
            float4 w = *(const float4*)(Wp + (size_t)k * ld);
            o0 = fmaf(h, w.x, o0);
            o1 = fmaf(h, w.y, o1);
            o2 = fmaf(h, w.z, o2);
            o3 = fmaf(h, w.w, o3);
        }

        if (b0 + r >= B) continue;
        float* pb = g_params + (size_t)(b0 + r) * (FF * 5);
        float o4[4] = {o0, o1, o2, o3};
        if (cg < 5) {
            #pragma unroll
            for (int ci = 0; ci < 4; ci++)
                pb[(cg * 4 + ci) * 5 + 2] = 2.f / (1.f + expf(-o4[ci]));
        } else if (cg < 10) {
            #pragma unroll
            for (int ci = 0; ci < 4; ci++) {
                float ang = tanhf(o4[ci]) * PI_F;
                int f = (cg - 5) * 4 + ci;
                pb[f * 5 + 0] = cosf(ang);
                pb[f * 5 + 1] = sinf(ang);
            }
        } else {
            #pragma unroll
            for (int ci = 0; ci < 4; ci++) {
                int o = (cg - 10) * 4 + ci;
                pb[(o >> 1) * 5 + 3 + (o & 1)] = tanhf(o4[ci]);
            }
        }
    }
}

// ---------------------------------------------------------------------------
// Kernel 2: trilinear sample, one CTA per batch element, block (18,18).
// Volume stored in SMEM as half2 pairs: pairs[z][py][j] = (V(j-1), V(j))
// with zero border. Each bilinear x-pair is ONE LDS.32.
// ---------------------------------------------------------------------------
__global__ __launch_bounds__(324) void adaat_sample_kernel(
    const float* __restrict__ fm, float* __restrict__ out)
{
    const int b   = blockIdx.x;
    const int tx  = threadIdx.x;      // 0..17
    const int ty  = threadIdx.y;      // 0..17
    const int tid = ty * WW + tx;

    __shared__ __half2 pairs[PVOL];   // 35280 B
    __shared__ float4  cfA[FF];       // axx, axy, cx, zw0
    __shared__ float4  cfB[FF];       // ayx, ayy, cy, zw1
    __shared__ int2    zb[FF];        // z0*441, z1*441

    // zero the pair volume (8820 half2 = 2205 float4)
    {
        float4* p4 = (float4*)pairs;
        for (int i = tid; i < PVOL / 4; i += HW)
            p4[i] = make_float4(0.f, 0.f, 0.f, 0.f);
    }
    __syncthreads();

    // fill interior: pairs[z][ty+1][tx+1] = (V(tx), V(tx+1)); col 0 = (0, V(0))
    {
        const float* src = fm + (size_t)b * VOL + ty * WW + tx;
        __half2* dst = pairs + (ty + 1) * PROW + (tx + 1);
        #pragma unroll
        for (int z = 0; z < FF; z++) {
            float val   = src[z * HW];
            float right = (tx < WW - 1) ? src[z * HW + 1] : 0.f;
            dst[z * PLAY] = __floats2half2_rn(val, right);
            if (tx == 0)
                pairs[z * PLAY + (ty + 1) * PROW] = __floats2half2_rn(0.f, val);
        }
    }

    // per-channel coefficients
    if (tid < FF) {
        const float* p = g_params + (size_t)(b * FF + tid) * 5;
        float c = p[0], s = p[1], sc = p[2], txp = p[3], typ = p[4];
        float kk  = sc * (2.f / (WW - 1)) * (WW * 0.5f);
        float axx = c * kk,  axy = -s * kk;
        float ayx = s * kk,  ayy =  c * kk;
        float cx = (WW * 0.5f) * (txp - sc * c + sc * s) + (WW - 1) * 0.5f;
        float cy = (HH * 0.5f) * (typ - sc * s - sc * c) + (HH - 1) * 0.5f;

        float iz  = (float)tid * ((float)FF / (FF - 1)) - 0.5f;
        float z0f = floorf(iz);
        float wz  = iz - z0f;
        int   z0  = (int)z0f, z1 = z0 + 1;
        float w0  = (z0 >= 0 && z0 < FF) ? (1.f - wz) : 0.f;
        float w1  = (z1 >= 0 && z1 < FF) ? wz         : 0.f;
        int   zb0 = min(max(z0, 0), FF - 1) * PLAY;
        int   zb1 = min(max(z1, 0), FF - 1) * PLAY;

        cfA[tid] = make_float4(axx, axy, cx, w0);
        cfB[tid] = make_float4(ayx, ayy, cy, w1);
        zb[tid]  = make_int2(zb0, zb1);
    }
    __syncthreads();

    const float fx = (float)tx, fy = (float)ty;
    float* outb = out + (size_t)b * VOL + tid;

    #pragma unroll 4
    for (int f = 0; f < FF; f++) {
        float4 A  = cfA[f];
        float4 Bv = cfB[f];
        int2   zo = zb[f];

        float ix = fmaf(A.x,  fx, fmaf(A.y,  fy, A.z));
        float iy = fmaf(Bv.x, fx, fmaf(Bv.y, fy, Bv.z));
        ix = fminf(fmaxf(ix, -1.f), (float)WW);
        iy = fminf(fmaxf(iy, -1.f), (float)HH);

        int   x0 = __float2int_rd(ix);
        int   y0 = __float2int_rd(iy);
        float wx = ix - (float)x0;
        float wy = iy - (float)y0;

        // pair index: row py = y0+1, col j = x0+1
        int bo = y0 * PROW + x0 + (PROW + 1);

        float2 f00 = __half22float2(pairs[zo.x + bo]);
        float2 f01 = __half22float2(pairs[zo.x + bo + PROW]);
        float2 f10 = __half22float2(pairs[zo.y + bo]);
        float2 f11 = __half22float2(pairs[zo.y + bo + PROW]);

        // x-lerp, y-lerp, z-blend
        float h00 = fmaf(wx, f00.y - f00.x, f00.x);
        float h01 = fmaf(wx, f01.y - f01.x, f01.x);
        float h10 = fmaf(wx, f10.y - f10.x, f10.x);
        float h11 = fmaf(wx, f11.y - f11.x, f11.x);

        float s0 = fmaf(wy, h01 - h00, h00);
        float s1 = fmaf(wy, h11 - h10, h10);

        outb[f * HW] = fmaf(A.w, s0, Bv.w * s1);
    }
}

// ---------------------------------------------------------------------------
// Launch
// ---------------------------------------------------------------------------
extern "C" void kernel_launch(void* const* d_in, const int* in_sizes, int n_in,
                              void* d_out, int out_size)
{
    const float* feature_map = (const float*)d_in[0];
    const float* para_code   = (const float*)d_in[1];
    const float* W1          = (const float*)d_in[2];
    const float* b1          = (const float*)d_in[3];
    const float* Ws          = (const float*)d_in[4];
    const float* bs          = (const float*)d_in[5];
    const float* Wr          = (const float*)d_in[6];
    const float* br          = (const float*)d_in[7];
    const float* Wt          = (const float*)d_in[8];
    const float* bt          = (const float*)d_in[9];
    float*       out         = (float*)d_out;

    int B = in_sizes[1] / PP;
    if (B > MAXB) B = MAXB;

    cudaFuncSetAttribute(adaat_params_kernel,
                         cudaFuncAttributeMaxDynamicSharedMemorySize, SMEM_PAR);

    adaat_params_kernel<<<(B + ROWS - 1) / ROWS, 256, SMEM_PAR>>>(
        para_code, B, W1, b1, Ws, bs, Wr, br, Wt, bt);
    adaat_sample_kernel<<<B, dim3(WW, HH)>>>(feature_map, out);
}

// round 5
// speedup vs baseline: 1.6732x; 1.6732x over previous
#include <cuda_runtime.h>
#include <cuda_bf16.h>
#include <cuda_fp16.h>
#include <math.h>

// Problem constants
#define PP   256
#define FF   20
#define HH   18
#define WW   18
#define HW   (HH*WW)      // 324
#define VOL  (FF*HH*WW)   // 6480
#define MAXB 4096
#define PI_F 3.14159f

// Padded pair volume for the sampler
#define PROW 21
#define PLAY (PROW*PROW)  // 441
#define PVOL (FF*PLAY)    // 8820 half2

// Device scratch
__device__ float g_h[MAXB * PP];            // hidden activations (4 MB)
__device__ float g_params[MAXB * FF * 5];   // c, s, scale, tx, ty per (b,f)

// ---------------------------------------------------------------------------
// f32x2 helpers (FFMA2 via PTX)
// ---------------------------------------------------------------------------
typedef unsigned long long u64;

__device__ __forceinline__ u64 pack2(float lo, float hi) {
    u64 d;
    asm("mov.b64 %0, {%1, %2};" : "=l"(d)
        : "r"(__float_as_uint(lo)), "r"(__float_as_uint(hi)));
    return d;
}
__device__ __forceinline__ u64 pack2dup(float v) {
    u64 d;
    asm("mov.b64 %0, {%1, %1};" : "=l"(d) : "r"(__float_as_uint(v)));
    return d;
}
__device__ __forceinline__ u64 fma2(u64 a, u64 b, u64 c) {
    u64 d;
    asm("fma.rn.f32x2 %0, %1, %2, %3;" : "=l"(d) : "l"(a), "l"(b), "l"(c));
    return d;
}
__device__ __forceinline__ float2 unpack2(u64 v) {
    unsigned lo, hi;
    asm("mov.b64 {%0, %1}, %2;" : "=r"(lo), "=r"(hi) : "l"(v));
    float2 f; f.x = __uint_as_float(lo); f.y = __uint_as_float(hi);
    return f;
}

// ---------------------------------------------------------------------------
// Kernel 1: h = relu(pc @ W1 + b1)   — classic tiled SGEMM
// BM=64, BN=64, BK=32, 256 threads, thread tile 4x4 (FFMA2 col pairs).
// grid = (ceil(B/64), 4)
// ---------------------------------------------------------------------------
#define K1_BM 64
#define K1_BN 64
#define K1_BK 32
#define K1_AS 68        // smem row stride (floats), 16B-aligned, bank-staggered

__global__ __launch_bounds__(256) void adaat_hidden_kernel(
    const float* __restrict__ pc, int B,
    const float* __restrict__ W1, const float* __restrict__ b1)
{
    __shared__ float As[K1_BK * K1_AS];   // [kk][row]
    __shared__ float Bs[K1_BK * K1_AS];   // [kk][col]

    const int b0  = blockIdx.x * K1_BM;
    const int n0  = blockIdx.y * K1_BN;
    const int tid = threadIdx.x;
    const int tc  = tid & 15;      // col group 0..15
    const int tr  = tid >> 4;      // row group 0..15

    u64 acc[4][2];
    {
        float4 bj = *(const float4*)(b1 + n0 + tc * 4);
        u64 lo = pack2(bj.x, bj.y), hi = pack2(bj.z, bj.w);
        #pragma unroll
        for (int i = 0; i < 4; i++) { acc[i][0] = lo; acc[i][1] = hi; }
    }

    for (int kt = 0; kt < PP; kt += K1_BK) {
        // load A tile: pc[b0+row][kt+kk] -> As[kk][row]
        #pragma unroll
        for (int p = 0; p < 8; p++) {
            int idx = p * 256 + tid;
            int row = idx >> 5;            // /32
            int kk  = idx & 31;
            float v = (b0 + row < B) ? pc[(size_t)(b0 + row) * PP + kt + kk] : 0.f;
            As[kk * K1_AS + row] = v;
        }
        // load B tile: W1[kt+kk][n0+col] -> Bs[kk][col]
        #pragma unroll
        for (int p = 0; p < 8; p++) {
            int idx = p * 256 + tid;
            int kk  = idx >> 6;            // /64
            int col = idx & 63;
            Bs[kk * K1_AS + col] = W1[(size_t)(kt + kk) * PP + n0 + col];
        }
        __syncthreads();

        #pragma unroll
        for (int kk = 0; kk < K1_BK; kk++) {
            float4 a = *(const float4*)(As + kk * K1_AS + tr * 4);
            float4 w = *(const float4*)(Bs + kk * K1_AS + tc * 4);
            u64 wlo = pack2(w.x, w.y), whi = pack2(w.z, w.w);
            u64 a0 = pack2dup(a.x), a1 = pack2dup(a.y);
            u64 a2 = pack2dup(a.z), a3 = pack2dup(a.w);
            acc[0][0] = fma2(a0, wlo, acc[0][0]); acc[0][1] = fma2(a0, whi, acc[0][1]);
            acc[1][0] = fma2(a1, wlo, acc[1][0]); acc[1][1] = fma2(a1, whi, acc[1][1]);
            acc[2][0] = fma2(a2, wlo, acc[2][0]); acc[2][1] = fma2(a2, whi, acc[2][1]);
            acc[3][0] = fma2(a3, wlo, acc[3][0]); acc[3][1] = fma2(a3, whi, acc[3][1]);
        }
        __syncthreads();
    }

    // relu + store
    #pragma unroll
    for (int i = 0; i < 4; i++) {
        int row = b0 + tr * 4 + i;
        if (row >= B) break;
        float2 v0 = unpack2(acc[i][0]);
        float2 v1 = unpack2(acc[i][1]);
        float4 o;
        o.x = fmaxf(v0.x, 0.f); o.y = fmaxf(v0.y, 0.f);
        o.z = fmaxf(v1.x, 0.f); o.w = fmaxf(v1.y, 0.f);
        *(float4*)(g_h + (size_t)row * PP + n0 + tc * 4) = o;
    }
}

// ---------------------------------------------------------------------------
// Kernel 2: heads — (B x 80) = h @ [Ws|Wr|Wt] + bias, then activations.
// BM=64 rows, 80 cols, BK=32, 320 threads, thread tile 4x4.
// ---------------------------------------------------------------------------
#define K2_BM 64
#define K2_BK 32
#define K2_AS 68        // A smem stride
#define K2_BS 84        // B smem stride (80 cols + pad, mult of 4)

__global__ __launch_bounds__(320) void adaat_heads_kernel(
    int B,
    const float* __restrict__ Ws, const float* __restrict__ bs,
    const float* __restrict__ Wr, const float* __restrict__ br,
    const float* __restrict__ Wt, const float* __restrict__ bt)
{
    __shared__ float As[K2_BK * K2_AS];   // [kk][row]
    __shared__ float Bs[K2_BK * K2_BS];   // [kk][col 0..79]

    const int b0  = blockIdx.x * K2_BM;
    const int tid = threadIdx.x;
    const int tc  = tid >> 4;      // 0..19 col group
    const int tr  = tid & 15;      // 0..15 row group

    u64 acc[4][2];
    {
        float4 bj;
        if (tc < 5)       bj = ((const float4*)bs)[tc];
        else if (tc < 10) bj = ((const float4*)br)[tc - 5];
        else              bj = ((const float4*)bt)[tc - 10];
        u64 lo = pack2(bj.x, bj.y), hi = pack2(bj.z, bj.w);
        #pragma unroll
        for (int i = 0; i < 4; i++) { acc[i][0] = lo; acc[i][1] = hi; }
    }

    for (int kt = 0; kt < PP; kt += K2_BK) {
        // A tile: g_h[b0+row][kt+kk] -> As[kk][row]   (2048 floats)
        for (int idx = tid; idx < K2_BM * K2_BK; idx += 320) {
            int row = idx >> 5;
            int kk  = idx & 31;
            float v = (b0 + row < B) ? g_h[(size_t)(b0 + row) * PP + kt + kk] : 0.f;
            As[kk * K2_AS + row] = v;
        }
        // B tile: combined [Ws|Wr|Wt] rows kt..kt+31 -> Bs[kk][0..79] (2560 floats)
        for (int idx = tid; idx < 80 * K2_BK; idx += 320) {
            int kk = idx / 80;
            int c  = idx - kk * 80;
            int k  = kt + kk;
            float v;
            if (c < 20)      v = Ws[(size_t)k * 20 + c];
            else if (c < 40) v = Wr[(size_t)k * 20 + (c - 20)];
            else             v = Wt[(size_t)k * 40 + (c - 40)];
            Bs[kk * K2_BS + c] = v;
        }
        __syncthreads();

        #pragma unroll
        for (int kk = 0; kk < K2_BK; kk++) {
            float4 a = *(const float4*)(As + kk * K2_AS + tr * 4);
            float4 w = *(const float4*)(Bs + kk * K2_BS + tc * 4);
            u64 wlo = pack2(w.x, w.y), whi = pack2(w.z, w.w);
            u64 a0 = pack2dup(a.x), a1 = pack2dup(a.y);
            u64 a2 = pack2dup(a.z), a3 = pack2dup(a.w);
            acc[0][0] = fma2(a0, wlo, acc[0][0]); acc[0][1] = fma2(a0, whi, acc[0][1]);
            acc[1][0] = fma2(a1, wlo, acc[1][0]); acc[1][1] = fma2(a1, whi, acc[1][1]);
            acc[2][0] = fma2(a2, wlo, acc[2][0]); acc[2][1] = fma2(a2, whi, acc[2][1]);
            acc[3][0] = fma2(a3, wlo, acc[3][0]); acc[3][1] = fma2(a3, whi, acc[3][1]);
        }
        __syncthreads();
    }

    // activations + scatter to g_params
    #pragma unroll
    for (int i = 0; i < 4; i++) {
        int row = b0 + tr * 4 + i;
        if (row >= B) break;
        float2 v0 = unpack2(acc[i][0]);
        float2 v1 = unpack2(acc[i][1]);
        float o4[4] = {v0.x, v0.y, v1.x, v1.y};
        float* pb = g_params + (size_t)row * (FF * 5);

        if (tc < 5) {                         // scale: cols tc*4..+3
            #pragma unroll
            for (int ci = 0; ci < 4; ci++)
                pb[(tc * 4 + ci) * 5 + 2] = 2.f / (1.f + expf(-o4[ci]));
        } else if (tc < 10) {                 // angle -> cos/sin
            #pragma unroll
            for (int ci = 0; ci < 4; ci++) {
                float ang = tanhf(o4[ci]) * PI_F;
                int f = (tc - 5) * 4 + ci;
                pb[f * 5 + 0] = cosf(ang);
                pb[f * 5 + 1] = sinf(ang);
            }
        } else {                              // trans
            #pragma unroll
            for (int ci = 0; ci < 4; ci++) {
                int o = (tc - 10) * 4 + ci;   // 0..39
                pb[(o >> 1) * 5 + 3 + (o & 1)] = tanhf(o4[ci]);
            }
        }
    }
}

// ---------------------------------------------------------------------------
// Kernel 3: trilinear sample, one CTA per batch element, block (18,18).
// Volume in SMEM as half2 pairs: pairs[z][py][j] = (V(j-1), V(j)), zero border.
// ---------------------------------------------------------------------------
__global__ __launch_bounds__(324) void adaat_sample_kernel(
    const float* __restrict__ fm, float* __restrict__ out)
{
    const int b   = blockIdx.x;
    const int tx  = threadIdx.x;      // 0..17
    const int ty  = threadIdx.y;      // 0..17
    const int tid = ty * WW + tx;

    __shared__ __half2 pairs[PVOL];   // 35280 B
    __shared__ float4  cfA[FF];       // axx, axy, cx, zw0
    __shared__ float4  cfB[FF];       // ayx, ayy, cy, zw1
    __shared__ int2    zb[FF];

    {
        float4* p4 = (float4*)pairs;
        for (int i = tid; i < PVOL / 4; i += HW)
            p4[i] = make_float4(0.f, 0.f, 0.f, 0.f);
    }
    __syncthreads();

    {
        const float* src = fm + (size_t)b * VOL + ty * WW + tx;
        __half2* dst = pairs + (ty + 1) * PROW + (tx + 1);
        #pragma unroll
        for (int z = 0; z < FF; z++) {
            float val   = src[z * HW];
            float right = (tx < WW - 1) ? src[z * HW + 1] : 0.f;
            dst[z * PLAY] = __floats2half2_rn(val, right);
            if (tx == 0)
                pairs[z * PLAY + (ty + 1) * PROW] = __floats2half2_rn(0.f, val);
        }
    }

    if (tid < FF) {
        const float* p = g_params + (size_t)(b * FF + tid) * 5;
        float c = p[0], s = p[1], sc = p[2], txp = p[3], typ = p[4];
        float kk  = sc * (2.f / (WW - 1)) * (WW * 0.5f);
        float axx = c * kk,  axy = -s * kk;
        float ayx = s * kk,  ayy =  c * kk;
        float cx = (WW * 0.5f) * (txp - sc * c + sc * s) + (WW - 1) * 0.5f;
        float cy = (HH * 0.5f) * (typ - sc * s - sc * c) + (HH - 1) * 0.5f;

        float iz  = (float)tid * ((float)FF / (FF - 1)) - 0.5f;
        float z0f = floorf(iz);
        float wz  = iz - z0f;
        int   z0  = (int)z0f, z1 = z0 + 1;
        float w0  = (z0 >= 0 && z0 < FF) ? (1.f - wz) : 0.f;
        float w1  = (z1 >= 0 && z1 < FF) ? wz         : 0.f;
        int   zb0 = min(max(z0, 0), FF - 1) * PLAY;
        int   zb1 = min(max(z1, 0), FF - 1) * PLAY;

        cfA[tid] = make_float4(axx, axy, cx, w0);
        cfB[tid] = make_float4(ayx, ayy, cy, w1);
        zb[tid]  = make_int2(zb0, zb1);
    }
    __syncthreads();

    const float fx = (float)tx, fy = (float)ty;
    float* outb = out + (size_t)b * VOL + tid;

    #pragma unroll 4
    for (int f = 0; f < FF; f++) {
        float4 A  = cfA[f];
        float4 Bv = cfB[f];
        int2   zo = zb[f];

        float ix = fmaf(A.x,  fx, fmaf(A.y,  fy, A.z));
        float iy = fmaf(Bv.x, fx, fmaf(Bv.y, fy, Bv.z));
        ix = fminf(fmaxf(ix, -1.f), (float)WW);
        iy = fminf(fmaxf(iy, -1.f), (float)HH);

        int   x0 = __float2int_rd(ix);
        int   y0 = __float2int_rd(iy);
        float wx = ix - (float)x0;
        float wy = iy - (float)y0;

        int bo = y0 * PROW + x0 + (PROW + 1);

        float2 f00 = __half22float2(pairs[zo.x + bo]);
        float2 f01 = __half22float2(pairs[zo.x + bo + PROW]);
        float2 f10 = __half22float2(pairs[zo.y + bo]);
        float2 f11 = __half22float2(pairs[zo.y + bo + PROW]);

        float h00 = fmaf(wx, f00.y - f00.x, f00.x);
        float h01 = fmaf(wx, f01.y - f01.x, f01.x);
        float h10 = fmaf(wx, f10.y - f10.x, f10.x);
        float h11 = fmaf(wx, f11.y - f11.x, f11.x);

        float s0 = fmaf(wy, h01 - h00, h00);
        float s1 = fmaf(wy, h11 - h10, h10);

        outb[f * HW] = fmaf(A.w, s0, Bv.w * s1);
    }
}

// ---------------------------------------------------------------------------
// Launch
// ---------------------------------------------------------------------------
extern "C" void kernel_launch(void* const* d_in, const int* in_sizes, int n_in,
                              void* d_out, int out_size)
{
    const float* feature_map = (const float*)d_in[0];
    const float* para_code   = (const float*)d_in[1];
    const float* W1          = (const float*)d_in[2];
    const float* b1          = (const float*)d_in[3];
    const float* Ws          = (const float*)d_in[4];
    const float* bs          = (const float*)d_in[5];
    const float* Wr          = (const float*)d_in[6];
    const float* br          = (const float*)d_in[7];
    const float* Wt          = (const float*)d_in[8];
    const float* bt          = (const float*)d_in[9];
    float*       out         = (float*)d_out;

    int B = in_sizes[1] / PP;
    if (B > MAXB) B = MAXB;

    dim3 g1((B + K1_BM - 1) / K1_BM, PP / K1_BN);
    adaat_hidden_kernel<<<g1, 256>>>(para_code, B, W1, b1);
    adaat_heads_kernel<<<(B + K2_BM - 1) / K2_BM, 320>>>(B, Ws, bs, Wr, br, Wt, bt);
    adaat_sample_kernel<<<B, dim3(WW, HH)>>>(feature_map, out);
}